// round 4
// baseline (speedup 1.0000x reference)
#include <cuda_runtime.h>
#include <math.h>

#define NB 4096
#define TT 1024
#define FEATN 30

// ---------------- scratch (static device globals; no allocation) ----------------
__device__ float g_fvs[NB * FEATN];
__device__ float g_fvd[NB * FEATN];
__device__ float g_fps[NB * FEATN];
__device__ float g_fpd[NB * FEATN];
__device__ float g_y30[NB * FEATN];

// ---------------- f32x2 helpers (Blackwell packed fp32 FMA, full-rate pipe) -----
__device__ __forceinline__ unsigned long long f2pack(float lo, float hi) {
    unsigned long long r;
    asm("mov.b64 %0, {%1,%2};" : "=l"(r) : "f"(lo), "f"(hi));
    return r;
}
__device__ __forceinline__ void f2fma(unsigned long long& d, unsigned long long a,
                                      unsigned long long b) {
    asm("fma.rn.f32x2 %0, %1, %2, %0;" : "+l"(d) : "l"(a), "l"(b));
}
__device__ __forceinline__ void f2unpack(unsigned long long v, float& lo, float& hi) {
    asm("mov.b64 {%0,%1}, %2;" : "=f"(lo), "=f"(hi) : "l"(v));
}

// =======================================================================
// Encode kernel: conv1d(C=3->64,K=3) + ReLU + mean_t, then two 64x30 heads.
// One block per (sample, modality). blockIdx.y: 0 = V, 1 = P.
// =======================================================================
__global__ __launch_bounds__(256) void encode_kernel(
    const float* __restrict__ S_V, const float* __restrict__ S_P,
    const float* __restrict__ Wc_v, const float* __restrict__ bc_v,
    const float* __restrict__ Ws_v, const float* __restrict__ bs_v,
    const float* __restrict__ Wd_v, const float* __restrict__ bd_v,
    const float* __restrict__ Wc_p, const float* __restrict__ bc_p,
    const float* __restrict__ Ws_p, const float* __restrict__ bs_p,
    const float* __restrict__ Wd_p, const float* __restrict__ bd_p)
{
    __shared__ __align__(16) float xs[3][1032];
    __shared__ float wcs[576];
    __shared__ float bcs[64];
    __shared__ float part[64][17];
    __shared__ float hsh[64];

    const int tid = threadIdx.x;
    const int b   = blockIdx.x;
    const int mo  = blockIdx.y;

    const float* S   = mo ? S_P  : S_V;
    const float* Wc  = mo ? Wc_p : Wc_v;
    const float* bc  = mo ? bc_p : bc_v;
    const float* Ws  = mo ? Ws_p : Ws_v;
    const float* bsv = mo ? bs_p : bs_v;
    const float* Wd  = mo ? Wd_p : Wd_v;
    const float* bdv = mo ? bd_p : bd_v;
    float* fs_out = mo ? g_fps : g_fvs;
    float* fd_out = mo ? g_fpd : g_fvd;

    for (int i = tid; i < 576; i += 256) wcs[i] = Wc[i];
    if (tid < 64) bcs[tid] = bc[tid];
    if (tid < 24) xs[tid / 8][1024 + (tid & 7)] = 0.f;   // zero pad tail
    const float* Sb = S + (size_t)b * 3072;
    for (int i = tid; i < 3072; i += 256) xs[i % 3][i / 3] = Sb[i];
    __syncthreads();

    const int cg = tid >> 4;          // 16 channel groups of 4
    const int tg = tid & 15;          // 16 time groups
    const int o0 = cg * 4;

    float w[36], bias4[4];
#pragma unroll
    for (int oi = 0; oi < 4; oi++) {
#pragma unroll
        for (int k9 = 0; k9 < 9; k9++) w[oi * 9 + k9] = wcs[(o0 + oi) * 9 + k9];
        bias4[oi] = bcs[o0 + oi];
    }

    float acc0 = 0.f, acc1 = 0.f, acc2 = 0.f, acc3 = 0.f;
    for (int j = 0; j < 16; j++) {
        const int t0 = tg * 4 + j * 64;           // multiple of 4, 0..1020
        float x[18];
#pragma unroll
        for (int c = 0; c < 3; c++) {
            float4 qa = *(const float4*)&xs[c][t0];
            float4 qb = *(const float4*)&xs[c][t0 + 4];
            x[c * 6 + 0] = qa.x; x[c * 6 + 1] = qa.y; x[c * 6 + 2] = qa.z;
            x[c * 6 + 3] = qa.w; x[c * 6 + 4] = qb.x; x[c * 6 + 5] = qb.y;
        }
        const bool full = (t0 + 3) < 1022;
#pragma unroll
        for (int oi = 0; oi < 4; oi++) {
            float v0 = bias4[oi], v1 = bias4[oi], v2 = bias4[oi], v3 = bias4[oi];
#pragma unroll
            for (int c = 0; c < 3; c++) {
                const float w0 = w[oi * 9 + c * 3];
                const float w1v = w[oi * 9 + c * 3 + 1];
                const float w2v = w[oi * 9 + c * 3 + 2];
                v0 = fmaf(w0, x[c * 6 + 0], v0); v0 = fmaf(w1v, x[c * 6 + 1], v0); v0 = fmaf(w2v, x[c * 6 + 2], v0);
                v1 = fmaf(w0, x[c * 6 + 1], v1); v1 = fmaf(w1v, x[c * 6 + 2], v1); v1 = fmaf(w2v, x[c * 6 + 3], v1);
                v2 = fmaf(w0, x[c * 6 + 2], v2); v2 = fmaf(w1v, x[c * 6 + 3], v2); v2 = fmaf(w2v, x[c * 6 + 4], v2);
                v3 = fmaf(w0, x[c * 6 + 3], v3); v3 = fmaf(w1v, x[c * 6 + 4], v3); v3 = fmaf(w2v, x[c * 6 + 5], v3);
            }
            float s;
            if (full) {
                s = fmaxf(v0, 0.f) + fmaxf(v1, 0.f) + fmaxf(v2, 0.f) + fmaxf(v3, 0.f);
            } else {
                s = 0.f;
                if (t0     < 1022) s += fmaxf(v0, 0.f);
                if (t0 + 1 < 1022) s += fmaxf(v1, 0.f);
                if (t0 + 2 < 1022) s += fmaxf(v2, 0.f);
            }
            if (oi == 0) acc0 += s; else if (oi == 1) acc1 += s;
            else if (oi == 2) acc2 += s; else acc3 += s;
        }
    }
    part[o0 + 0][tg] = acc0; part[o0 + 1][tg] = acc1;
    part[o0 + 2][tg] = acc2; part[o0 + 3][tg] = acc3;
    __syncthreads();

    if (tid < 64) {
        float s = 0.f;
#pragma unroll
        for (int g = 0; g < 16; g++) s += part[tid][g];
        hsh[tid] = s * (1.f / 1022.f);
    }
    __syncthreads();

    if (tid < 60) {
        const int  j2 = tid % 30;
        const bool first = tid < 30;
        const float* Wm = first ? Ws : Wd;
        float s = first ? bsv[j2] : bdv[j2];
        for (int i = 0; i < 64; i++) s = fmaf(hsh[i], Wm[i * 30 + j2], s);
        if (first) fs_out[b * 30 + j2] = s;
        else       fd_out[b * 30 + j2] = s;
    }
}

// =======================================================================
// Physical-model kernel: conv1d(3->64,K=5)+pool4 -> conv1d(64->30,K=5)+pool4
// -> mean -> y30.  One block per sample, 512 threads, dynamic smem.
// Inner loops use packed fma.rn.f32x2 (time-pair packing).
// =======================================================================
__global__ __launch_bounds__(512) void phys_kernel(
    const float* __restrict__ S_P1,
    const float* __restrict__ W1, const float* __restrict__ b1,
    const float* __restrict__ W2, const float* __restrict__ b2)
{
    extern __shared__ float sm[];
    float* xs   = sm;                 // [3][1032]
    float* p1   = xs + 3 * 1032;      // [64][256] pooled conv1 (bias included)
    float* w1s  = p1 + 64 * 256;      // [64*15]
    float* w2s  = w1s + 960;          // [(c*5+k)*32 + o]  (o padded to 32)
    float* part = w2s + 10240;        // [30][33]
    float* b1s  = part + 990;         // [64]

    const int tid = threadIdx.x;
    const int b   = blockIdx.x;

    for (int i = tid; i < 960; i += 512) w1s[i] = W1[i];
    if (tid < 64) b1s[tid] = b1[tid];
    for (int i = tid; i < 9600; i += 512) {
        int o = i / 320, ck = i % 320;
        w2s[ck * 32 + o] = W2[i];
    }
    const float* Sb = S_P1 + (size_t)b * 3072;
    for (int i = tid; i < 3072; i += 512) xs[(i % 3) * 1032 + i / 3] = Sb[i];
    __syncthreads();

    // -------- conv1 (K=5, C=3, O=64) fused with maxpool4 --------
    {
        const int cg = tid >> 4;       // 0..31 -> 2 channels each
        const int tg = tid & 15;
        const int o0 = cg * 2;
        float wA[15], wB[15];
#pragma unroll
        for (int i2 = 0; i2 < 15; i2++) {
            wA[i2] = w1s[o0 * 15 + i2];
            wB[i2] = w1s[(o0 + 1) * 15 + i2];
        }
        const float biasA = b1s[o0], biasB = b1s[o0 + 1];

        for (int m = 0; m < 16; m++) {
            const int j = tg + m * 16;            // pooled index 0..254
            if (j < 255) {
                const int t0 = 4 * j;
                unsigned long long aA01 = 0ull, aA23 = 0ull, aB01 = 0ull, aB23 = 0ull;
#pragma unroll
                for (int c = 0; c < 3; c++) {
                    const float* xr = xs + c * 1032 + t0;
                    float4 qa = *(const float4*)xr;
                    float4 qb = *(const float4*)(xr + 4);
                    float x0 = qa.x, x1 = qa.y, x2 = qa.z, x3 = qa.w;
                    float x4 = qb.x, x5 = qb.y, x6 = qb.z, x7 = qb.w;
                    unsigned long long Parr[7];
                    Parr[0] = f2pack(x0, x1); Parr[1] = f2pack(x1, x2);
                    Parr[2] = f2pack(x2, x3); Parr[3] = f2pack(x3, x4);
                    Parr[4] = f2pack(x4, x5); Parr[5] = f2pack(x5, x6);
                    Parr[6] = f2pack(x6, x7);
#pragma unroll
                    for (int k = 0; k < 5; k++) {
                        unsigned long long wa2 = f2pack(wA[c * 5 + k], wA[c * 5 + k]);
                        unsigned long long wb2 = f2pack(wB[c * 5 + k], wB[c * 5 + k]);
                        f2fma(aA01, Parr[k],     wa2);
                        f2fma(aA23, Parr[k + 2], wa2);
                        f2fma(aB01, Parr[k],     wb2);
                        f2fma(aB23, Parr[k + 2], wb2);
                    }
                }
                float u0, u1, u2, u3;
                f2unpack(aA01, u0, u1); f2unpack(aA23, u2, u3);
                p1[o0 * 256 + j] = fmaxf(fmaxf(u0, u1), fmaxf(u2, u3)) + biasA;
                f2unpack(aB01, u0, u1); f2unpack(aB23, u2, u3);
                p1[(o0 + 1) * 256 + j] = fmaxf(fmaxf(u0, u1), fmaxf(u2, u3)) + biasB;
            }
        }
    }
    __syncthreads();

    // -------- conv2 (K=5, C=64, O=30) fused with maxpool4 + mean --------
    {
        const int og  = tid % 15;     // 2 output channels each
        const int chn = tid / 15;     // 8 conv positions (2 pool windows)
        if (chn < 31) {
            const int o0 = og * 2, t0 = chn * 8;
            unsigned long long a0[4] = {0ull, 0ull, 0ull, 0ull};
            unsigned long long a1[4] = {0ull, 0ull, 0ull, 0ull};
            for (int c = 0; c < 64; c++) {
                const float* xr = p1 + c * 256 + t0;
                float4 qa = *(const float4*)xr;
                float4 qb = *(const float4*)(xr + 4);
                float4 qc = *(const float4*)(xr + 8);
                float x[12] = {qa.x, qa.y, qa.z, qa.w, qb.x, qb.y, qb.z, qb.w,
                               qc.x, qc.y, qc.z, qc.w};
                unsigned long long P[11];
#pragma unroll
                for (int i2 = 0; i2 < 11; i2++) P[i2] = f2pack(x[i2], x[i2 + 1]);
                const float* wrow = w2s + o0;
#pragma unroll
                for (int k = 0; k < 5; k++) {
                    const float w0v = wrow[(c * 5 + k) * 32];
                    const float w1v = wrow[(c * 5 + k) * 32 + 1];
                    unsigned long long w02 = f2pack(w0v, w0v);
                    unsigned long long w12 = f2pack(w1v, w1v);
                    f2fma(a0[0], P[k],     w02); f2fma(a0[1], P[k + 2], w02);
                    f2fma(a0[2], P[k + 4], w02); f2fma(a0[3], P[k + 6], w02);
                    f2fma(a1[0], P[k],     w12); f2fma(a1[1], P[k + 2], w12);
                    f2fma(a1[2], P[k + 4], w12); f2fma(a1[3], P[k + 6], w12);
                }
            }
            float v0, v1, v2, v3, v4, v5, v6, v7;
            f2unpack(a0[0], v0, v1); f2unpack(a0[1], v2, v3);
            f2unpack(a0[2], v4, v5); f2unpack(a0[3], v6, v7);
            part[o0 * 33 + chn] = fmaxf(fmaxf(v0, v1), fmaxf(v2, v3)) +
                                  fmaxf(fmaxf(v4, v5), fmaxf(v6, v7));
            f2unpack(a1[0], v0, v1); f2unpack(a1[1], v2, v3);
            f2unpack(a1[2], v4, v5); f2unpack(a1[3], v6, v7);
            part[(o0 + 1) * 33 + chn] = fmaxf(fmaxf(v0, v1), fmaxf(v2, v3)) +
                                        fmaxf(fmaxf(v4, v5), fmaxf(v6, v7));
        }
    }
    __syncthreads();

    if (tid < 30) {
        float s = 0.f;
        for (int ch2 = 0; ch2 < 31; ch2++) s += part[tid * 33 + ch2];
        g_y30[b * 30 + tid] = s * (1.f / 62.f) + b2[tid];
    }
}

// =======================================================================
// Fusion kernel: Wsp heads, logsumexp soft-OR, masked MQ attention, output.
// One warp per sample; 8 samples per 256-thread block.
// =======================================================================
__global__ __launch_bounds__(256) void fuse_kernel(
    const int* __restrict__ pairs,
    const float* __restrict__ Wsp, const float* __restrict__ bsp,
    const float* __restrict__ Wa, const float* __restrict__ ba,
    const float* __restrict__ Wf, const float* __restrict__ bf,
    float* __restrict__ out)
{
    __shared__ float Wsp_s[900], bsp_s[30], Wa_s[5760], ba_s[192], Wf_s[128], bf_s[4];
    __shared__ float ain[8][4][32];

    const int tid = threadIdx.x;
    for (int i = tid; i < 900; i += 256) Wsp_s[i] = Wsp[i];
    for (int i = tid; i < 5760; i += 256) Wa_s[i] = Wa[i];
    if (tid < 30)  bsp_s[tid] = bsp[tid];
    if (tid < 192) ba_s[tid]  = ba[tid];
    if (tid < 128) Wf_s[tid]  = Wf[tid];
    if (tid < 4)   bf_s[tid]  = bf[tid];
    __syncthreads();

    const int warp = tid >> 5, lane = tid & 31;
    const int b = blockIdx.x * 8 + warp;

    float fvs = 0.f, fps = 0.f, fvd = 0.f, fpd = 0.f, yv = 0.f;
    if (lane < 30) {
        fvs = g_fvs[b * 30 + lane];
        fps = g_fps[b * 30 + lane];
        fvd = g_fvd[b * 30 + lane];
        fpd = g_fpd[b * 30 + lane];
        yv  = g_y30[b * 30 + lane];
    }

    // shared projection Wsp on both shared features
    float h1 = (lane < 30) ? bsp_s[lane] : 0.f;
    float h2 = h1;
    for (int i = 0; i < 30; i++) {
        float av = __shfl_sync(0xffffffffu, fvs, i);
        float bv = __shfl_sync(0xffffffffu, fps, i);
        float wv = (lane < 30) ? Wsp_s[i * 30 + lane] : 0.f;
        h1 = fmaf(av, wv, h1);
        h2 = fmaf(bv, wv, h2);
    }

    const int   pr = pairs[b];
    const float pf = (float)pr;
    // logsumexp soft-OR fusion
    const float h12 = h1 + h2;
    float m1 = fmaxf(h12, fmaxf(h1, h2));
    float lse1 = m1 + logf(2.f * expf(h12 - m1) + expf(h1 - m1) + expf(h2 - m1));
    float m2 = fmaxf(0.f, fmaxf(h1, h2));
    float lse2 = m2 + logf(2.f * expf(0.f - m2) + expf(h1 - m2) + expf(h2 - m2));
    const float favg = pf * (lse1 - lse2) + (1.f - pf) * h2;

    if (lane < 30) {
        ain[warp][0][lane] = fpd;
        ain[warp][1][lane] = favg;
        ain[warp][2][lane] = yv;
        ain[warp][3][lane] = fvd;
    }
    __syncwarp();

    // qkvs = attn_in @ Wa + ba ;  r[t][g] holds column g*32+lane
    float r[4][6];
#pragma unroll
    for (int g = 0; g < 6; g++) {
        float s0 = ba_s[g * 32 + lane], s1 = s0, s2 = s0, s3 = s0;
        for (int i = 0; i < 30; i++) {
            const float wv = Wa_s[i * 192 + g * 32 + lane];
            s0 = fmaf(ain[warp][0][i], wv, s0);
            s1 = fmaf(ain[warp][1][i], wv, s1);
            s2 = fmaf(ain[warp][2][i], wv, s2);
            s3 = fmaf(ain[warp][3][i], wv, s3);
        }
        r[0][g] = s0; r[1][g] = s1; r[2][g] = s2; r[3][g] = s3;
    }

    // q mean (4 tokens if paired, first 3 otherwise); d = lane
    const float qsum3 = r[0][0] + r[1][0] + r[2][0];
    const float qm = pf * 0.25f * (qsum3 + r[3][0]) + (1.f - pf) * (qsum3 * (1.f / 3.f));

    // logits[n][t] = <ks[n][t], qm> / sqrt(32)
    float lg[4][4];
#pragma unroll
    for (int n = 0; n < 4; n++) {
#pragma unroll
        for (int t = 0; t < 4; t++) {
            float p = r[t][2 + n] * qm;
#pragma unroll
            for (int off = 16; off; off >>= 1) p += __shfl_xor_sync(0xffffffffu, p, off);
            lg[n][t] = p * 0.17677669529663687f;
        }
    }

#pragma unroll
    for (int n = 0; n < 4; n++) {
        const float l0 = lg[n][0], l1 = lg[n][1], l2 = lg[n][2], l3 = lg[n][3];
        float m = fmaxf(fmaxf(l0, l1), l2);
        if (pr) m = fmaxf(m, l3);
        const float e0 = expf(l0 - m), e1 = expf(l1 - m), e2 = expf(l2 - m);
        const float e3 = pr ? expf(l3 - m) : 0.f;
        const float inv = 1.f / (e0 + e1 + e2 + e3);
        const float ff = (e0 * r[0][1] + e1 * r[1][1] + e2 * r[2][1] + e3 * r[3][1]) * inv;
        float p = ff * Wf_s[lane * 4 + n];
#pragma unroll
        for (int off = 16; off; off >>= 1) p += __shfl_xor_sync(0xffffffffu, p, off);
        if (lane == 0) out[b * 4 + n] = p + bf_s[n];
    }
}

// =======================================================================
extern "C" void kernel_launch(void* const* d_in, const int* in_sizes, int n_in,
                              void* d_out, int out_size)
{
    (void)in_sizes; (void)n_in; (void)out_size;
    const int*   pairs = (const int*)d_in[0];
    const float* S_V  = (const float*)d_in[1];
    const float* S_P  = (const float*)d_in[2];
    const float* S_P1 = (const float*)d_in[3];
    const float* Wc_v = (const float*)d_in[4];  const float* bc_v = (const float*)d_in[5];
    const float* Ws_v = (const float*)d_in[6];  const float* bs_v = (const float*)d_in[7];
    const float* Wd_v = (const float*)d_in[8];  const float* bd_v = (const float*)d_in[9];
    const float* Wc_p = (const float*)d_in[10]; const float* bc_p = (const float*)d_in[11];
    const float* Ws_p = (const float*)d_in[12]; const float* bs_p = (const float*)d_in[13];
    const float* Wd_p = (const float*)d_in[14]; const float* bd_p = (const float*)d_in[15];
    const float* Wsp  = (const float*)d_in[16]; const float* bsp  = (const float*)d_in[17];
    const float* W1   = (const float*)d_in[18]; const float* b1   = (const float*)d_in[19];
    const float* W2   = (const float*)d_in[20]; const float* b2   = (const float*)d_in[21];
    const float* Wa   = (const float*)d_in[22]; const float* ba   = (const float*)d_in[23];
    const float* Wf   = (const float*)d_in[24]; const float* bf   = (const float*)d_in[25];
    float* out = (float*)d_out;

    const int PHYS_SMEM = (3 * 1032 + 64 * 256 + 960 + 10240 + 990 + 64) * 4;
    cudaFuncSetAttribute(phys_kernel, cudaFuncAttributeMaxDynamicSharedMemorySize, PHYS_SMEM);

    encode_kernel<<<dim3(NB, 2), 256>>>(S_V, S_P,
                                        Wc_v, bc_v, Ws_v, bs_v, Wd_v, bd_v,
                                        Wc_p, bc_p, Ws_p, bs_p, Wd_p, bd_p);
    phys_kernel<<<NB, 512, PHYS_SMEM>>>(S_P1, W1, b1, W2, b2);
    fuse_kernel<<<NB / 8, 256>>>(pairs, Wsp, bsp, Wa, ba, Wf, bf, out);
}

// round 6
// speedup vs baseline: 2.4738x; 2.4738x over previous
#include <cuda_runtime.h>
#include <math.h>

#define NB 4096
#define TT 1024
#define FEATN 30

// ---------------- scratch (static device globals; no allocation) ----------------
__device__ float g_fvs[NB * FEATN];
__device__ float g_fvd[NB * FEATN];
__device__ float g_fps[NB * FEATN];
__device__ float g_fpd[NB * FEATN];
__device__ float g_y30[NB * FEATN];
// conv2 weights, duplicated as (o,o+1) pairs: [(c*5+k)][og] float2, og padded to 16
__device__ float2 g_w2dup[320 * 16];

// ---------------- f32x2 helpers (Blackwell packed fp32 FMA, full-rate pipe) -----
typedef unsigned long long ull_t;
__device__ __forceinline__ ull_t f2pack(float lo, float hi) {
    ull_t r;
    asm("mov.b64 %0, {%1,%2};" : "=l"(r) : "f"(lo), "f"(hi));
    return r;
}
__device__ __forceinline__ ull_t f2dup(float v) { return f2pack(v, v); }
__device__ __forceinline__ void f2fma(ull_t& d, ull_t a, ull_t b) {
    asm("fma.rn.f32x2 %0, %1, %2, %0;" : "+l"(d) : "l"(a), "l"(b));
}
__device__ __forceinline__ void f2unpack(ull_t v, float& lo, float& hi) {
    asm("mov.b64 {%0,%1}, %2;" : "=f"(lo), "=f"(hi) : "l"(v));
}

// =======================================================================
// Prep: build duplicated conv2 weight pairs. W2: [30][64][5] row-major.
// g_w2dup[(c*5+k)*16 + og] = { W2[2og][c][k], W2[2og+1][c][k] }
// =======================================================================
__global__ void prep_w2(const float* __restrict__ W2) {
    int i = blockIdx.x * 256 + threadIdx.x;   // 320*15 = 4800 entries
    if (i < 4800) {
        int ck = i / 15, og = i - ck * 15;
        g_w2dup[ck * 16 + og] =
            make_float2(W2[(2 * og) * 320 + ck], W2[(2 * og + 1) * 320 + ck]);
    }
}

// =======================================================================
// Encode kernel: conv1d(C=3->64,K=3) + ReLU + mean_t, then two 64x30 heads.
// One block per (sample, modality). blockIdx.y: 0 = V, 1 = P.
// f32x2 with output-channel-pair packing; weights register-resident.
// =======================================================================
__global__ __launch_bounds__(256) void encode_kernel(
    const float* __restrict__ S_V, const float* __restrict__ S_P,
    const float* __restrict__ Wc_v, const float* __restrict__ bc_v,
    const float* __restrict__ Ws_v, const float* __restrict__ bs_v,
    const float* __restrict__ Wd_v, const float* __restrict__ bd_v,
    const float* __restrict__ Wc_p, const float* __restrict__ bc_p,
    const float* __restrict__ Ws_p, const float* __restrict__ bs_p,
    const float* __restrict__ Wd_p, const float* __restrict__ bd_p)
{
    __shared__ __align__(16) float xs[3][1032];
    __shared__ float part[64][9];
    __shared__ float hsh[64];

    const int tid = threadIdx.x;
    const int b   = blockIdx.x;
    const int mo  = blockIdx.y;

    const float* S   = mo ? S_P  : S_V;
    const float* Wc  = mo ? Wc_p : Wc_v;
    const float* bc  = mo ? bc_p : bc_v;
    const float* Ws  = mo ? Ws_p : Ws_v;
    const float* bsv = mo ? bs_p : bs_v;
    const float* Wd  = mo ? Wd_p : Wd_v;
    const float* bdv = mo ? bd_p : bd_v;
    float* fs_out = mo ? g_fps : g_fvs;
    float* fd_out = mo ? g_fpd : g_fvd;

    if (tid < 24) xs[tid / 8][1024 + (tid & 7)] = 0.f;   // zero pad tail
    const float* Sb = S + (size_t)b * 3072;
    for (int i = tid; i < 3072; i += 256) xs[i % 3][i / 3] = Sb[i];
    __syncthreads();

    const int pg = tid >> 3;          // 32 output-channel pairs
    const int tg = tid & 7;           // 8 time groups
    const int o0 = pg * 2;

    // register-resident packed weights: pair (o0, o0+1)
    ull_t WU[9];
#pragma unroll
    for (int i = 0; i < 9; i++)
        WU[i] = f2pack(Wc[o0 * 9 + i], Wc[o0 * 9 + 9 + i]);
    const ull_t Bp = f2pack(bc[o0], bc[o0 + 1]);

    float s0 = 0.f, s1 = 0.f;
    for (int m = 0; m < 32; m++) {
        const int t0 = 4 * tg + 32 * m;          // 0..1020, step 4
        ull_t A[4] = {Bp, Bp, Bp, Bp};
#pragma unroll
        for (int c = 0; c < 3; c++) {
            float4 qa = *(const float4*)&xs[c][t0];
            float2 qb = *(const float2*)&xs[c][t0 + 4];
            ull_t X[6];
            X[0] = f2dup(qa.x); X[1] = f2dup(qa.y); X[2] = f2dup(qa.z);
            X[3] = f2dup(qa.w); X[4] = f2dup(qb.x); X[5] = f2dup(qb.y);
#pragma unroll
            for (int k = 0; k < 3; k++) {
                const ull_t W = WU[c * 3 + k];
#pragma unroll
                for (int p = 0; p < 4; p++) f2fma(A[p], X[p + k], W);
            }
        }
        float u[4], v[4];
#pragma unroll
        for (int p = 0; p < 4; p++) f2unpack(A[p], u[p], v[p]);
        if (t0 + 3 < 1022) {
#pragma unroll
            for (int p = 0; p < 4; p++) {
                s0 += fmaxf(u[p], 0.f);
                s1 += fmaxf(v[p], 0.f);
            }
        } else {
#pragma unroll
            for (int p = 0; p < 4; p++) {
                if (t0 + p < 1022) {
                    s0 += fmaxf(u[p], 0.f);
                    s1 += fmaxf(v[p], 0.f);
                }
            }
        }
    }
    part[o0][tg]     = s0;
    part[o0 + 1][tg] = s1;
    __syncthreads();

    if (tid < 64) {
        float s = 0.f;
#pragma unroll
        for (int g = 0; g < 8; g++) s += part[tid][g];
        hsh[tid] = s * (1.f / 1022.f);
    }
    __syncthreads();

    if (tid < 60) {
        const int  j2 = tid % 30;
        const bool first = tid < 30;
        const float* Wm = first ? Ws : Wd;
        float s = first ? bsv[j2] : bdv[j2];
        for (int i = 0; i < 64; i++) s = fmaf(hsh[i], Wm[i * 30 + j2], s);
        if (first) fs_out[b * 30 + j2] = s;
        else       fd_out[b * 30 + j2] = s;
    }
}

// =======================================================================
// Physical-model kernel: conv1d(3->64,K=5)+pool4 -> conv1d(64->30,K=5)+pool4
// -> mean -> y30.  One block per sample, 512 threads, ~82KB dynamic smem
// (2 CTAs/SM).  f32x2 with output-channel-pair packing; conv1 weights in
// registers, conv2 weights as uniform LDG.64 of pre-duplicated pairs.
// =======================================================================
__global__ __launch_bounds__(512) void phys_kernel(
    const float* __restrict__ S_P1,
    const float* __restrict__ W1, const float* __restrict__ b1,
    const float* __restrict__ b2)
{
    extern __shared__ float sm[];
    float* xs   = sm;                 // [3][1032]            3096
    float* p1   = xs + 3096;          // [64][256]            16384
    float* part = p1 + 16384;         // [30][31]             930

    const int tid = threadIdx.x;
    const int b   = blockIdx.x;

    const float* Sb = S_P1 + (size_t)b * 3072;
    for (int i = tid; i < 3072; i += 512) xs[(i % 3) * 1032 + i / 3] = Sb[i];
    __syncthreads();

    // -------- conv1 (K=5, C=3, O=64) fused with maxpool4, o-pair packed ------
    {
        const int pg = tid >> 4;       // 32 output-channel pairs
        const int tg = tid & 15;
        const int o0 = pg * 2;
        ull_t WU[15];
#pragma unroll
        for (int i = 0; i < 15; i++)
            WU[i] = f2pack(W1[o0 * 15 + i], W1[o0 * 15 + 15 + i]);
        const ull_t Bp = f2pack(b1[o0], b1[o0 + 1]);

        for (int m = 0; m < 16; m++) {
            const int j = tg + m * 16;            // pooled index 0..254
            if (j < 255) {
                const int t0 = 4 * j;
                ull_t A[4] = {Bp, Bp, Bp, Bp};
#pragma unroll
                for (int c = 0; c < 3; c++) {
                    const float* xr = xs + c * 1032 + t0;
                    float4 qa = *(const float4*)xr;
                    float4 qb = *(const float4*)(xr + 4);
                    ull_t X[8];
                    X[0] = f2dup(qa.x); X[1] = f2dup(qa.y); X[2] = f2dup(qa.z);
                    X[3] = f2dup(qa.w); X[4] = f2dup(qb.x); X[5] = f2dup(qb.y);
                    X[6] = f2dup(qb.z); X[7] = f2dup(qb.w);
#pragma unroll
                    for (int k = 0; k < 5; k++) {
                        const ull_t W = WU[c * 5 + k];
#pragma unroll
                        for (int p = 0; p < 4; p++) f2fma(A[p], X[p + k], W);
                    }
                }
                float u[4], v[4];
#pragma unroll
                for (int p = 0; p < 4; p++) f2unpack(A[p], u[p], v[p]);
                p1[o0 * 256 + j] =
                    fmaxf(fmaxf(u[0], u[1]), fmaxf(u[2], u[3]));
                p1[(o0 + 1) * 256 + j] =
                    fmaxf(fmaxf(v[0], v[1]), fmaxf(v[2], v[3]));
            }
        }
    }
    __syncthreads();

    // -------- conv2 (K=5, C=64, O=30) fused with maxpool4 + mean, o-pair ----
    {
        const int og  = tid & 15;     // 15 output-channel pairs (og==15 idle)
        const int chn = tid >> 4;     // 31 groups of 8 conv positions
        if (og < 15 && chn < 31) {
            const int o0 = og * 2, t0 = chn * 8;
            const ull_t* w2u = (const ull_t*)g_w2dup;
            ull_t A[8] = {0ull, 0ull, 0ull, 0ull, 0ull, 0ull, 0ull, 0ull};
            for (int c = 0; c < 64; c++) {
                const float* xr = p1 + c * 256 + t0;
                float4 qa = *(const float4*)xr;
                float4 qb = *(const float4*)(xr + 4);
                float4 qc = *(const float4*)(xr + 8);
                ull_t X[12];
                X[0] = f2dup(qa.x);  X[1] = f2dup(qa.y);  X[2]  = f2dup(qa.z);
                X[3] = f2dup(qa.w);  X[4] = f2dup(qb.x);  X[5]  = f2dup(qb.y);
                X[6] = f2dup(qb.z);  X[7] = f2dup(qb.w);  X[8]  = f2dup(qc.x);
                X[9] = f2dup(qc.y);  X[10] = f2dup(qc.z); X[11] = f2dup(qc.w);
                const int base = c * 80 + og;     // (c*5)*16 + og
#pragma unroll
                for (int k = 0; k < 5; k++) {
                    const ull_t W = __ldg(&w2u[base + k * 16]);
#pragma unroll
                    for (int p = 0; p < 8; p++) f2fma(A[p], X[p + k], W);
                }
            }
            float u[8], v[8];
#pragma unroll
            for (int p = 0; p < 8; p++) f2unpack(A[p], u[p], v[p]);
            part[o0 * 31 + chn] =
                fmaxf(fmaxf(u[0], u[1]), fmaxf(u[2], u[3])) +
                fmaxf(fmaxf(u[4], u[5]), fmaxf(u[6], u[7]));
            part[(o0 + 1) * 31 + chn] =
                fmaxf(fmaxf(v[0], v[1]), fmaxf(v[2], v[3])) +
                fmaxf(fmaxf(v[4], v[5]), fmaxf(v[6], v[7]));
        }
    }
    __syncthreads();

    if (tid < 30) {
        float s = 0.f;
        for (int ch2 = 0; ch2 < 31; ch2++) s += part[tid * 31 + ch2];
        g_y30[b * 30 + tid] = s * (1.f / 62.f) + b2[tid];
    }
}

// =======================================================================
// Fusion kernel: Wsp heads, logsumexp soft-OR, masked MQ attention, output.
// One warp per sample; 8 samples per 256-thread block.
// =======================================================================
__global__ __launch_bounds__(256) void fuse_kernel(
    const int* __restrict__ pairs,
    const float* __restrict__ Wsp, const float* __restrict__ bsp,
    const float* __restrict__ Wa, const float* __restrict__ ba,
    const float* __restrict__ Wf, const float* __restrict__ bf,
    float* __restrict__ out)
{
    __shared__ float Wsp_s[900], bsp_s[30], Wa_s[5760], ba_s[192], Wf_s[128], bf_s[4];
    __shared__ float ain[8][4][32];

    const int tid = threadIdx.x;
    for (int i = tid; i < 900; i += 256) Wsp_s[i] = Wsp[i];
    for (int i = tid; i < 5760; i += 256) Wa_s[i] = Wa[i];
    if (tid < 30)  bsp_s[tid] = bsp[tid];
    if (tid < 192) ba_s[tid]  = ba[tid];
    if (tid < 128) Wf_s[tid]  = Wf[tid];
    if (tid < 4)   bf_s[tid]  = bf[tid];
    __syncthreads();

    const int warp = tid >> 5, lane = tid & 31;
    const int b = blockIdx.x * 8 + warp;

    float fvs = 0.f, fps = 0.f, fvd = 0.f, fpd = 0.f, yv = 0.f;
    if (lane < 30) {
        fvs = g_fvs[b * 30 + lane];
        fps = g_fps[b * 30 + lane];
        fvd = g_fvd[b * 30 + lane];
        fpd = g_fpd[b * 30 + lane];
        yv  = g_y30[b * 30 + lane];
    }

    // shared projection Wsp on both shared features
    float h1 = (lane < 30) ? bsp_s[lane] : 0.f;
    float h2 = h1;
    for (int i = 0; i < 30; i++) {
        float av = __shfl_sync(0xffffffffu, fvs, i);
        float bv = __shfl_sync(0xffffffffu, fps, i);
        float wv = (lane < 30) ? Wsp_s[i * 30 + lane] : 0.f;
        h1 = fmaf(av, wv, h1);
        h2 = fmaf(bv, wv, h2);
    }

    const int   pr = pairs[b];
    const float pf = (float)pr;
    // logsumexp soft-OR fusion
    const float h12 = h1 + h2;
    float m1 = fmaxf(h12, fmaxf(h1, h2));
    float lse1 = m1 + logf(2.f * expf(h12 - m1) + expf(h1 - m1) + expf(h2 - m1));
    float m2 = fmaxf(0.f, fmaxf(h1, h2));
    float lse2 = m2 + logf(2.f * expf(0.f - m2) + expf(h1 - m2) + expf(h2 - m2));
    const float favg = pf * (lse1 - lse2) + (1.f - pf) * h2;

    if (lane < 30) {
        ain[warp][0][lane] = fpd;
        ain[warp][1][lane] = favg;
        ain[warp][2][lane] = yv;
        ain[warp][3][lane] = fvd;
    }
    __syncwarp();

    // qkvs = attn_in @ Wa + ba ;  r[t][g] holds column g*32+lane
    float r[4][6];
#pragma unroll
    for (int g = 0; g < 6; g++) {
        float s0 = ba_s[g * 32 + lane], s1 = s0, s2 = s0, s3 = s0;
        for (int i = 0; i < 30; i++) {
            const float wv = Wa_s[i * 192 + g * 32 + lane];
            s0 = fmaf(ain[warp][0][i], wv, s0);
            s1 = fmaf(ain[warp][1][i], wv, s1);
            s2 = fmaf(ain[warp][2][i], wv, s2);
            s3 = fmaf(ain[warp][3][i], wv, s3);
        }
        r[0][g] = s0; r[1][g] = s1; r[2][g] = s2; r[3][g] = s3;
    }

    // q mean (4 tokens if paired, first 3 otherwise); d = lane
    const float qsum3 = r[0][0] + r[1][0] + r[2][0];
    const float qm = pf * 0.25f * (qsum3 + r[3][0]) + (1.f - pf) * (qsum3 * (1.f / 3.f));

    // logits[n][t] = <ks[n][t], qm> / sqrt(32)
    float lg[4][4];
#pragma unroll
    for (int n = 0; n < 4; n++) {
#pragma unroll
        for (int t = 0; t < 4; t++) {
            float p = r[t][2 + n] * qm;
#pragma unroll
            for (int off = 16; off; off >>= 1) p += __shfl_xor_sync(0xffffffffu, p, off);
            lg[n][t] = p * 0.17677669529663687f;
        }
    }

#pragma unroll
    for (int n = 0; n < 4; n++) {
        const float l0 = lg[n][0], l1 = lg[n][1], l2 = lg[n][2], l3 = lg[n][3];
        float m = fmaxf(fmaxf(l0, l1), l2);
        if (pr) m = fmaxf(m, l3);
        const float e0 = expf(l0 - m), e1 = expf(l1 - m), e2 = expf(l2 - m);
        const float e3 = pr ? expf(l3 - m) : 0.f;
        const float inv = 1.f / (e0 + e1 + e2 + e3);
        const float ff = (e0 * r[0][1] + e1 * r[1][1] + e2 * r[2][1] + e3 * r[3][1]) * inv;
        float p = ff * Wf_s[lane * 4 + n];
#pragma unroll
        for (int off = 16; off; off >>= 1) p += __shfl_xor_sync(0xffffffffu, p, off);
        if (lane == 0) out[b * 4 + n] = p + bf_s[n];
    }
}

// =======================================================================
extern "C" void kernel_launch(void* const* d_in, const int* in_sizes, int n_in,
                              void* d_out, int out_size)
{
    (void)in_sizes; (void)n_in; (void)out_size;
    const int*   pairs = (const int*)d_in[0];
    const float* S_V  = (const float*)d_in[1];
    const float* S_P  = (const float*)d_in[2];
    const float* S_P1 = (const float*)d_in[3];
    const float* Wc_v = (const float*)d_in[4];  const float* bc_v = (const float*)d_in[5];
    const float* Ws_v = (const float*)d_in[6];  const float* bs_v = (const float*)d_in[7];
    const float* Wd_v = (const float*)d_in[8];  const float* bd_v = (const float*)d_in[9];
    const float* Wc_p = (const float*)d_in[10]; const float* bc_p = (const float*)d_in[11];
    const float* Ws_p = (const float*)d_in[12]; const float* bs_p = (const float*)d_in[13];
    const float* Wd_p = (const float*)d_in[14]; const float* bd_p = (const float*)d_in[15];
    const float* Wsp  = (const float*)d_in[16]; const float* bsp  = (const float*)d_in[17];
    const float* W1   = (const float*)d_in[18]; const float* b1   = (const float*)d_in[19];
    const float* W2   = (const float*)d_in[20]; const float* b2   = (const float*)d_in[21];
    const float* Wa   = (const float*)d_in[22]; const float* ba   = (const float*)d_in[23];
    const float* Wf   = (const float*)d_in[24]; const float* bf   = (const float*)d_in[25];
    float* out = (float*)d_out;

    const int PHYS_SMEM = (3096 + 16384 + 930) * 4;   // ~81.6 KB -> 2 CTAs/SM
    cudaFuncSetAttribute(phys_kernel, cudaFuncAttributeMaxDynamicSharedMemorySize, PHYS_SMEM);

    prep_w2<<<19, 256>>>(W2);
    encode_kernel<<<dim3(NB, 2), 256>>>(S_V, S_P,
                                        Wc_v, bc_v, Ws_v, bs_v, Wd_v, bd_v,
                                        Wc_p, bc_p, Ws_p, bs_p, Wd_p, bd_p);
    phys_kernel<<<NB, 512, PHYS_SMEM>>>(S_P1, W1, b1, b2);
    fuse_kernel<<<NB / 8, 256>>>(pairs, Wsp, bsp, Wa, ba, Wf, bf, out);
}